// round 3
// baseline (speedup 1.0000x reference)
#include <cuda_runtime.h>
#include <cuda_bf16.h>
#include <cstdint>

#define HH   256
#define WW   256
#define NP   (HH * WW)
#define NG   1024
#define MM   50
#define NCH  150
#define NCHF 152          // padded: 76 f32x2 pairs
#define NPAIR 76
#define TILE 16
#define NTX  (WW / TILE)

// ---------------------------------------------------------------------------
// Single fused kernel: per-CTA gaussian prep + cull + sparse render.
// One CTA per 16x16 tile, 1 thread per pixel, f32x2 packed accumulate.
// ---------------------------------------------------------------------------
__global__ __launch_bounds__(256) void render_fused(
    const float* __restrict__ xyz,
    const float* __restrict__ chol,
    const float* __restrict__ opac,
    const float* __restrict__ fdc,
    const int*   __restrict__ cid_p,
    float*       __restrict__ out)
{
    __shared__ float    s_prm[NG][6];                 // 24 KB: cx,cy,c1,c2,c3,op
    __shared__ unsigned s_mask[32];
    __shared__ int      s_off[32];
    __shared__ int      s_count;
    __shared__ short    s_list[NG];                   // 2 KB
    __shared__ __align__(16) float s_feat[16][NCHF];  // 9.5 KB

    const int tid  = threadIdx.x;
    const int lane = tid & 31;
    const int wid  = tid >> 5;
    const int tile = blockIdx.x;
    const int tx0  = (tile & (NTX - 1)) * TILE;
    const int ty0  = (tile >> 4) * TILE;
    const int cid  = *cid_p;

    // ---- Phase A: compute all gaussian params (redundant per CTA) + cull ----
    const float fxl = (float)tx0, fxh = (float)(tx0 + TILE - 1);
    const float fyl = (float)ty0, fyh = (float)(ty0 + TILE - 1);
#pragma unroll
    for (int j = 0; j < 4; j++) {
        int g = tid + j * 256;
        float2 xr = ((const float2*)xyz)[g];
        float x  = tanhf(xr.x);
        float y  = tanhf(xr.y);
        float l1 = chol[3 * g + 0] + 0.5f;
        float l2 = chol[3 * g + 1];
        float l3 = chol[3 * g + 2] + 0.5f;
        float a = l1 * l1;                 // Sigma_xx
        float b = l1 * l2;
        float c = l2 * l2 + l3 * l3;       // Sigma_yy
        float det = a * c - b * b;
        float c1 = c / det;
        float c2 = -b / det;
        float c3 = a / det;
        float cx = 0.5f * ((x + 1.0f) * (float)WW - 1.0f);
        float cy = 0.5f * ((y + 1.0f) * (float)HH - 1.0f);
        float op = opac[g];
        s_prm[g][0] = cx; s_prm[g][1] = cy; s_prm[g][2] = c1;
        s_prm[g][3] = c2; s_prm[g][4] = c3; s_prm[g][5] = op;

        // alpha >= 1/255 <=> sigma <= T = ln(255*op); ellipse extent:
        // |dx| <= sqrt(2*T*Sigma_xx), |dy| <= sqrt(2*T*Sigma_yy). +2 px margin.
        bool hit = false;
        float T = __logf(255.0f * op);
        if (T > 0.0f) {
            float hx = sqrtf(2.0f * T * a) + 2.0f;
            float hy = sqrtf(2.0f * T * c) + 2.0f;
            hit = (cx - hx <= fxh) && (cx + hx >= fxl) &&
                  (cy - hy <= fyh) && (cy + hy >= fyl);
        }
        unsigned m = __ballot_sync(0xffffffffu, hit);
        if (lane == 0) s_mask[j * 8 + wid] = m;
    }
    __syncthreads();

    // ---- ordered compaction of hit bitmask (deterministic) ----
    if (tid < 32) {
        int c = __popc(s_mask[tid]);
        int x = c;
#pragma unroll
        for (int d = 1; d < 32; d <<= 1) {
            int y = __shfl_up_sync(0xffffffffu, x, d);
            if (lane >= d) x += y;
        }
        s_off[tid] = x - c;
        if (tid == 31) s_count = x;
    }
    __syncthreads();
    if (tid < 32) {
        unsigned m = s_mask[tid];
        int o = s_off[tid];
        int base = tid * 32;
        while (m) {
            int b = __ffs(m) - 1;
            m &= m - 1;
            s_list[o++] = (short)(base + b);
        }
    }
    __syncthreads();
    const int count = s_count;

    const float fx = (float)(tx0 + (tid & 15));
    const float fy = (float)(ty0 + (tid >> 4));

    unsigned long long acc[NPAIR];
#pragma unroll
    for (int k = 0; k < NPAIR; k++) acc[k] = 0ull;

    // ---- main loop: chunks of 16 culled gaussians ----
    for (int c0 = 0; c0 < count; c0 += 16) {
        int nc = min(16, count - c0);
        // gather features directly from fdc (L2-resident, high MLP)
        for (int i = tid; i < nc * NCHF; i += 256) {
            int g = i / NCHF;
            int t = i - g * NCHF;
            float v = 0.0f;
            if (t < NCH) {
                int m = t / 3;
                int cc = t - 3 * m;
                int n = (int)s_list[c0 + g];
                v = fdc[(((size_t)cid * MM + m) * NG + n) * 3 + cc];
            }
            s_feat[g][t] = v;
        }
        __syncthreads();

        for (int g = 0; g < nc; g++) {
            int n = (int)s_list[c0 + g];
            float cx = s_prm[n][0], cy = s_prm[n][1];
            float c1 = s_prm[n][2], c2 = s_prm[n][3], c3 = s_prm[n][4];
            float op = s_prm[n][5];
            float dx = cx - fx;
            float dy = cy - fy;
            float sig = 0.5f * (c1 * dx * dx + c3 * dy * dy) + c2 * dx * dy;
            float al = fminf(0.999f, op * __expf(-sig));
            al = (sig >= 0.0f && al >= (1.0f / 255.0f)) ? al : 0.0f;
            unsigned long long ap;
            asm("mov.b64 %0, {%1,%1};" : "=l"(ap) : "r"(__float_as_uint(al)));
            const ulonglong2* fp = (const ulonglong2*)&s_feat[g][0];
#pragma unroll
            for (int k = 0; k < NPAIR / 2; k++) {
                ulonglong2 f2 = fp[k];
                asm("fma.rn.f32x2 %0, %1, %2, %0;" : "+l"(acc[2*k])   : "l"(ap), "l"(f2.x));
                asm("fma.rn.f32x2 %0, %1, %2, %0;" : "+l"(acc[2*k+1]) : "l"(ap), "l"(f2.y));
            }
        }
        __syncthreads();
    }

    // ---- epilogue: unpack pairs, 150 coalesced channel-strided stores ----
    const int pofs = (ty0 + (tid >> 4)) * WW + tx0 + (tid & 15);
#pragma unroll
    for (int k = 0; k < NCH / 2; k++) {      // pairs 0..74 -> channels 0..149
        unsigned lo, hi;
        asm("mov.b64 {%0,%1}, %2;" : "=r"(lo), "=r"(hi) : "l"(acc[k]));
        out[(size_t)(2 * k)     * NP + pofs] = __uint_as_float(lo);
        out[(size_t)(2 * k + 1) * NP + pofs] = __uint_as_float(hi);
    }
}

// ---------------------------------------------------------------------------
extern "C" void kernel_launch(void* const* d_in, const int* in_sizes, int n_in,
                              void* d_out, int out_size) {
    const float* xyz  = (const float*)d_in[0];  // [N,2]
    const float* chol = (const float*)d_in[1];  // [N,3]
    const float* opac = (const float*)d_in[2];  // [N,1]
    const float* fdc  = (const float*)d_in[3];  // [K,M,N,3]
    const int*   cid  = (const int*)d_in[4];    // scalar

    render_fused<<<(HH / TILE) * (WW / TILE), 256>>>(xyz, chol, opac, fdc, cid,
                                                     (float*)d_out);
}

// round 4
// speedup vs baseline: 1.6250x; 1.6250x over previous
#include <cuda_runtime.h>
#include <cuda_bf16.h>
#include <cstdint>

#define HH   256
#define WW   256
#define NP   (HH * WW)
#define NG   1024
#define MM   50
#define NCH  150
#define NCHF 152              // padded channels: 76 f32x2 pairs
#define TPX  16               // tile width
#define TPY  8                // tile height
#define NTX  (WW / TPX)       // 16
#define NTY  (HH / TPY)       // 32
#define HPAIR 38              // f32x2 pairs per half-thread

// Scratch (device globals; no allocation allowed)
__device__ float g_params[NG * 8];      // cx, cy, c1, c2, c3, op, pad, pad
__device__ int4  g_bbox[NG];            // x0, x1, y0, y1 (inclusive, conservative)
__device__ float g_featT[NG * NCHF];    // [n][152] channel-major, zero-padded

// ---------------------------------------------------------------------------
// Prep: blocks 0..3 -> gaussian params+bbox; blocks 4.. -> feature transpose
// ---------------------------------------------------------------------------
__global__ void prep_all(const float* __restrict__ xyz,
                         const float* __restrict__ chol,
                         const float* __restrict__ opac,
                         const float* __restrict__ fdc,
                         const int*   __restrict__ cid_p) {
    const int tid = threadIdx.x;
    if (blockIdx.x < 4) {
        int n = blockIdx.x * 256 + tid;
        float2 xr = ((const float2*)xyz)[n];
        float x  = tanhf(xr.x);
        float y  = tanhf(xr.y);
        float l1 = chol[3 * n + 0] + 0.5f;
        float l2 = chol[3 * n + 1];
        float l3 = chol[3 * n + 2] + 0.5f;
        float a = l1 * l1;
        float b = l1 * l2;
        float c = l2 * l2 + l3 * l3;
        float det = a * c - b * b;
        float c1 = c / det;
        float c2 = -b / det;
        float c3 = a / det;
        float cx = 0.5f * ((x + 1.0f) * (float)WW - 1.0f);
        float cy = 0.5f * ((y + 1.0f) * (float)HH - 1.0f);
        float op = opac[n];
        float* p = &g_params[n * 8];
        p[0] = cx; p[1] = cy; p[2] = c1; p[3] = c2; p[4] = c3; p[5] = op;
        p[6] = 0.0f; p[7] = 0.0f;

        // alpha >= 1/255 <=> sigma <= T = ln(255*op); ellipse extents
        // hx = sqrt(2*T*Sigma_xx), hy = sqrt(2*T*Sigma_yy); +2 px margin
        int4 bb;
        float T = __logf(255.0f * op);
        if (T > 0.0f) {
            float hx = sqrtf(2.0f * T * a) + 2.0f;
            float hy = sqrtf(2.0f * T * c) + 2.0f;
            bb.x = max(0, (int)floorf(cx - hx));
            bb.y = min(WW - 1, (int)ceilf(cx + hx));
            bb.z = max(0, (int)floorf(cy - hy));
            bb.w = min(HH - 1, (int)ceilf(cy + hy));
        } else {
            bb.x = WW; bb.y = -1; bb.z = HH; bb.w = -1;
        }
        g_bbox[n] = bb;
    } else {
        int i = (blockIdx.x - 4) * 256 + tid;
        if (i < NG * NCHF) {
            int n = i / NCHF;
            int t = i - n * NCHF;
            float v = 0.0f;
            if (t < NCH) {
                int m  = t / 3;
                int cc = t - 3 * m;
                int cid = *cid_p;
                v = fdc[(((size_t)cid * MM + m) * NG + n) * 3 + cc];
            }
            g_featT[i] = v;
        }
    }
}

// ---------------------------------------------------------------------------
// Render: one CTA per 16x8 tile, 2 threads per pixel (half channels each),
// f32x2 packed accumulate, deterministic ordered culling.
// ---------------------------------------------------------------------------
__global__ __launch_bounds__(256, 2) void render(float* __restrict__ out) {
    __shared__ unsigned s_mask[32];
    __shared__ int      s_off[32];
    __shared__ int      s_count;
    __shared__ short    s_list[NG];
    __shared__ __align__(16) float4 s_feat[16][NCHF / 4];  // 9.5 KB
    __shared__ float    s_cp[16][6];

    const int tid  = threadIdx.x;
    const int lane = tid & 31;
    const int wid  = tid >> 5;
    const int tx0  = (blockIdx.x & (NTX - 1)) * TPX;
    const int ty0  = (blockIdx.x >> 4) * TPY;

    // ---- cull: 1024 bbox-vs-tile tests, ordered bitmask ----
#pragma unroll
    for (int j = 0; j < 4; j++) {
        int g = tid + j * 256;
        int4 bb = g_bbox[g];
        bool hit = (bb.x <= tx0 + TPX - 1) && (bb.y >= tx0) &&
                   (bb.z <= ty0 + TPY - 1) && (bb.w >= ty0);
        unsigned m = __ballot_sync(0xffffffffu, hit);
        if (lane == 0) s_mask[j * 8 + wid] = m;
    }
    __syncthreads();
    if (tid < 32) {
        int c = __popc(s_mask[tid]);
        int x = c;
#pragma unroll
        for (int d = 1; d < 32; d <<= 1) {
            int y = __shfl_up_sync(0xffffffffu, x, d);
            if (lane >= d) x += y;
        }
        s_off[tid] = x - c;
        if (tid == 31) s_count = x;
    }
    __syncthreads();
    if (tid < 32) {
        unsigned m = s_mask[tid];
        int o = s_off[tid];
        int base = tid * 32;
        while (m) {
            int b = __ffs(m) - 1;
            m &= m - 1;
            s_list[o++] = (short)(base + b);
        }
    }
    __syncthreads();
    const int count = s_count;

    const int  pix  = tid >> 1;            // 0..127
    const int  half = tid & 1;             // channel half
    const float fx  = (float)(tx0 + (pix & (TPX - 1)));
    const float fy  = (float)(ty0 + (pix >> 4));

    unsigned long long acc[HPAIR];
#pragma unroll
    for (int k = 0; k < HPAIR; k++) acc[k] = 0ull;

    // ---- main loop: chunks of 16 culled gaussians ----
    for (int c0 = 0; c0 < count; c0 += 16) {
        int nc = min(16, count - c0);
        for (int i = tid; i < nc * (NCHF / 4); i += 256) {
            int g = i / (NCHF / 4);
            int k = i - g * (NCHF / 4);
            s_feat[g][k] = ((const float4*)g_featT)[(int)s_list[c0 + g] * (NCHF / 4) + k];
        }
        if (tid < nc * 6) {
            int g = tid / 6;
            int k = tid - g * 6;
            s_cp[g][k] = g_params[(int)s_list[c0 + g] * 8 + k];
        }
        __syncthreads();

        for (int g = 0; g < nc; g++) {
            float cx = s_cp[g][0], cy = s_cp[g][1];
            float c1 = s_cp[g][2], c2 = s_cp[g][3], c3 = s_cp[g][4];
            float op = s_cp[g][5];
            float dx = cx - fx;
            float dy = cy - fy;
            float sig = 0.5f * (c1 * dx * dx + c3 * dy * dy) + c2 * dx * dy;
            float al = fminf(0.999f, op * __expf(-sig));
            al = (sig >= 0.0f && al >= (1.0f / 255.0f)) ? al : 0.0f;
            if (__ballot_sync(0xffffffffu, al > 0.0f) == 0u) continue;
            unsigned long long ap;
            asm("mov.b64 %0, {%1,%1};" : "=l"(ap) : "r"(__float_as_uint(al)));
            // this half's 38 pairs = 76 floats at offset half*76 (16B aligned)
            const ulonglong2* fp =
                (const ulonglong2*)((const float*)&s_feat[g][0] + half * (2 * HPAIR));
#pragma unroll
            for (int k = 0; k < HPAIR / 2; k++) {
                ulonglong2 f2 = fp[k];
                asm("fma.rn.f32x2 %0, %1, %2, %0;" : "+l"(acc[2*k])   : "l"(ap), "l"(f2.x));
                asm("fma.rn.f32x2 %0, %1, %2, %0;" : "+l"(acc[2*k+1]) : "l"(ap), "l"(f2.y));
            }
        }
        __syncthreads();
    }

    // ---- epilogue: unpack, coalesced channel-strided stores ----
    const int pofs = (ty0 + (pix >> 4)) * WW + tx0 + (pix & (TPX - 1));
#pragma unroll
    for (int k = 0; k < HPAIR; k++) {
        int kp = half * HPAIR + k;          // global pair index
        if (kp < NCH / 2) {                 // pair 75 is padding
            unsigned lo, hi;
            asm("mov.b64 {%0,%1}, %2;" : "=r"(lo), "=r"(hi) : "l"(acc[k]));
            out[(size_t)(2 * kp)     * NP + pofs] = __uint_as_float(lo);
            out[(size_t)(2 * kp + 1) * NP + pofs] = __uint_as_float(hi);
        }
    }
}

// ---------------------------------------------------------------------------
extern "C" void kernel_launch(void* const* d_in, const int* in_sizes, int n_in,
                              void* d_out, int out_size) {
    const float* xyz  = (const float*)d_in[0];  // [N,2]
    const float* chol = (const float*)d_in[1];  // [N,3]
    const float* opac = (const float*)d_in[2];  // [N,1]
    const float* fdc  = (const float*)d_in[3];  // [K,M,N,3]
    const int*   cid  = (const int*)d_in[4];    // scalar

    prep_all<<<4 + (NG * NCHF + 255) / 256, 256>>>(xyz, chol, opac, fdc, cid);
    render<<<NTX * NTY, 256>>>((float*)d_out);
}